// round 6
// baseline (speedup 1.0000x reference)
#include <cuda_runtime.h>
#include <cuda_fp16.h>
#include <math.h>

#define NFFT    8192
#define LSEQ    4095
#define DMODEL  768
#define NLAYERS 12
#define TTHR    512
#define SPAD    9216                      // 8192 + 2*(8192/16) padding
#define AP(p)   ((p) + (((p) >> 4) << 1))
#define CONV_SMEM  ((SPAD + 4096) * sizeof(float2))
#define WSPEC_SMEM (SPAD * sizeof(float2))

// ---------------- device scratch ----------------
__device__ float2 g_x[DMODEL * LSEQ];                      // packed {b0,b1}, (D,L)
__device__ uint4  g_w[(size_t)NLAYERS * DMODEL * 2048];    // fp16 spectra, perm order, 302 MB
__device__ float2 g_tw[512];                               // W_8192^k

// ---------------- packed f32x2 complex helpers ----------------
__device__ __forceinline__ unsigned long long pk2(float2 v) {
    unsigned long long u;
    asm("mov.b64 %0, {%1, %2};" : "=l"(u) : "f"(v.x), "f"(v.y));
    return u;
}
__device__ __forceinline__ float2 upk2(unsigned long long u) {
    float2 v;
    asm("mov.b64 {%0, %1}, %2;" : "=f"(v.x), "=f"(v.y) : "l"(u));
    return v;
}
// lane-wise complex add/sub via packed f32x2 (1 instr instead of 2 FADD)
__device__ __forceinline__ float2 cadd(float2 a, float2 b) {
    unsigned long long r;
    asm("add.rn.f32x2 %0, %1, %2;" : "=l"(r) : "l"(pk2(a)), "l"(pk2(b)));
    return upk2(r);
}
__device__ __forceinline__ float2 csub(float2 a, float2 b) {
    unsigned long long r;
    asm("sub.rn.f32x2 %0, %1, %2;" : "=l"(r) : "l"(pk2(a)), "l"(pk2(b)));
    return upk2(r);
}
// lane-wise fma: a*b + c
__device__ __forceinline__ float2 lfma(float2 a, float2 b, float2 c) {
    unsigned long long r;
    asm("fma.rn.f32x2 %0, %1, %2, %3;" : "=l"(r) : "l"(pk2(a)), "l"(pk2(b)), "l"(pk2(c)));
    return upk2(r);
}
__device__ __forceinline__ float2 cmul(float2 a, float2 b) {
    return make_float2(fmaf(a.x, b.x, -a.y * b.y), fmaf(a.x, b.y, a.y * b.x));
}
__device__ __forceinline__ float2 cmulf(float2 a, float c, float s) {
    return make_float2(fmaf(a.x, c, -a.y * s), fmaf(a.x, s, a.y * c));
}
__device__ __forceinline__ float2 conjf(float2 a) { return make_float2(a.x, -a.y); }
__device__ __forceinline__ float2 h2f2(unsigned u) {
    __half2 h = *reinterpret_cast<__half2*>(&u);
    return __half22float2(h);
}
__device__ __forceinline__ unsigned f2h2(float2 v) {
    __half2 h = __floats2half2_rn(v.x, v.y);
    return *reinterpret_cast<unsigned*>(&h);
}

// 4-bit bit reversal (involution)
__device__ __forceinline__ constexpr int br4c(int r) {
    return ((r & 1) << 3) | ((r & 2) << 1) | ((r & 4) >> 1) | ((r & 8) >> 3);
}
__device__ __forceinline__ int br4(int r) {
    return ((r & 1) << 3) | ((r & 2) << 1) | ((r & 4) >> 1) | ((r & 8) >> 3);
}

// position <-> frequency maps for decomposition 16(512) x 16(32) x 2(16) x 16(1)
__device__ __forceinline__ int posk(int p) {
    return (p >> 9) | (((p >> 5) & 15) << 4) | (((p >> 4) & 1) << 8) | (br4(p & 15) << 9);
}
__device__ __forceinline__ int kpos(int k) {
    return ((k & 15) << 9) | (((k >> 4) & 15) << 5) | (((k >> 8) & 1) << 4) | br4((k >> 9) & 15);
}

// multiply by W16^k (forward) or conj (inverse)
__device__ __forceinline__ float2 twk(float2 a, int k, bool cj) {
    const float c1 = 0.92387953251128675613f;
    const float s1 = 0.38268343236508977173f;
    const float r2 = 0.70710678118654752440f;
    float c, s;
    switch (k & 7) {
        case 0: return a;
        case 1: c =  c1; s = -s1; break;
        case 2: c =  r2; s = -r2; break;
        case 3: c =  s1; s = -c1; break;
        case 4: return cj ? make_float2(-a.y, a.x) : make_float2(a.y, -a.x);
        case 5: c = -s1; s = -c1; break;
        case 6: c = -r2; s = -r2; break;
        default: c = -c1; s = -s1; break;
    }
    if (cj) s = -s;
    return cmulf(a, c, s);
}

// forward DIF DFT16: natural input, slot q holds bin br4(q)
__device__ __forceinline__ void dft16_dif(float2* v) {
    #pragma unroll
    for (int i = 0; i < 8; i++) {
        float2 a = v[i], b = v[i + 8];
        v[i] = cadd(a, b); v[i + 8] = twk(csub(a, b), i, false);
    }
    #pragma unroll
    for (int B = 0; B < 16; B += 8)
        #pragma unroll
        for (int i = 0; i < 4; i++) {
            float2 a = v[B + i], b = v[B + i + 4];
            v[B + i] = cadd(a, b); v[B + i + 4] = twk(csub(a, b), 2 * i, false);
        }
    #pragma unroll
    for (int B = 0; B < 16; B += 4)
        #pragma unroll
        for (int i = 0; i < 2; i++) {
            float2 a = v[B + i], b = v[B + i + 2];
            v[B + i] = cadd(a, b); v[B + i + 2] = twk(csub(a, b), 4 * i, false);
        }
    #pragma unroll
    for (int B = 0; B < 16; B += 2) {
        float2 a = v[B], b = v[B + 1];
        v[B] = cadd(a, b); v[B + 1] = csub(a, b);
    }
}

// inverse DIT DFT16 with conj twiddles: slot q holds bin br4(q), natural output
__device__ __forceinline__ void dft16_dit_conj(float2* v) {
    #pragma unroll
    for (int B = 0; B < 16; B += 2) {
        float2 a = v[B], b = v[B + 1];
        v[B] = cadd(a, b); v[B + 1] = csub(a, b);
    }
    #pragma unroll
    for (int B = 0; B < 16; B += 4)
        #pragma unroll
        for (int i = 0; i < 2; i++) {
            float2 a = v[B + i], b = twk(v[B + i + 2], 4 * i, true);
            v[B + i] = cadd(a, b); v[B + i + 2] = csub(a, b);
        }
    #pragma unroll
    for (int B = 0; B < 16; B += 8)
        #pragma unroll
        for (int i = 0; i < 4; i++) {
            float2 a = v[B + i], b = twk(v[B + i + 4], 2 * i, true);
            v[B + i] = cadd(a, b); v[B + i + 4] = csub(a, b);
        }
    #pragma unroll
    for (int i = 0; i < 8; i++) {
        float2 a = v[i], b = twk(v[i + 8], i, true);
        v[i] = cadd(a, b); v[i + 8] = csub(a, b);
    }
}

// apply forward twiddle chain in place (slot br4c(r) gets *wa^r), two chains
__device__ __forceinline__ void chain_fwd(float2* v, float2 wa) {
    float2 w2 = cmul(wa, wa);
    float2 eo = wa, ee = w2;
    v[br4c(1)] = cmul(v[br4c(1)], eo);
    #pragma unroll
    for (int r = 2; r < 16; r += 2) {
        v[br4c(r)] = cmul(v[br4c(r)], ee);
        eo = cmul(eo, w2);
        v[br4c(r + 1)] = cmul(v[br4c(r + 1)], eo);
        ee = cmul(ee, w2);
    }
}

// pass B forward: radix-16 @32 with twiddle + fused radix-2 @16 via shfl
__device__ __forceinline__ void passB_fwd(float2* S, int baseB, float2 waB,
                                          bool lo, float2 w32) {
    float2 v[16];
    #pragma unroll
    for (int j = 0; j < 16; j++) v[j] = S[AP(baseB + (j << 5))];
    dft16_dif(v);
    chain_fwd(v, waB);
    #pragma unroll
    for (int q = 0; q < 16; q++) {
        float2 val = v[q], oth;
        oth.x = __shfl_xor_sync(0xFFFFFFFFu, val.x, 16);
        oth.y = __shfl_xor_sync(0xFFFFFFFFu, val.y, 16);
        float2 sum = cadd(val, oth);
        float2 dif = cmul(csub(oth, val), w32);
        v[q] = lo ? sum : dif;
    }
    #pragma unroll
    for (int r = 0; r < 16; r++) S[AP(baseB + (r << 5))] = v[br4c(r)];
}

// pass B inverse: undo radix-2 @16 (shfl, conj W32), conj twiddle, DIT-16 @32
__device__ __forceinline__ void passB_inv(float2* S, int baseB, float2 cwB,
                                          bool lo, float2 cw32) {
    float2 v[16];
    #pragma unroll
    for (int r = 0; r < 16; r++) v[br4c(r)] = S[AP(baseB + (r << 5))];
    #pragma unroll
    for (int q = 0; q < 16; q++) {
        float2 tmp = lo ? v[q] : cmul(v[q], cw32);
        float2 oth;
        oth.x = __shfl_xor_sync(0xFFFFFFFFu, tmp.x, 16);
        oth.y = __shfl_xor_sync(0xFFFFFFFFu, tmp.y, 16);
        v[q] = lo ? cadd(tmp, oth) : csub(oth, tmp);
    }
    chain_fwd(v, cwB);
    dft16_dit_conj(v);
    #pragma unroll
    for (int j = 0; j < 16; j++) S[AP(baseB + (j << 5))] = v[j];
}

// ---------------- kernel 0: twiddle table ----------------
__global__ void tw_init_kernel() {
    int k = threadIdx.x;
    float s, c;
    sincospif(-(float)k / 4096.0f, &s, &c);
    g_tw[k] = make_float2(c, s);
}

// ---------------- kernel 1: embedding -> g_x packed (D,L) ----------------
__global__ void __launch_bounds__(1024) embed_kernel(const int* __restrict__ ids,
                                                     const float* __restrict__ emb,
                                                     const float* __restrict__ pos) {
    __shared__ float t0[32][33], t1[32][33];
    int l = blockIdx.x * 32 + threadIdx.y;
    int d = blockIdx.y * 32 + threadIdx.x;
    float v0 = 0.f, v1 = 0.f;
    if (l < LSEQ) {
        int id0 = ids[l], id1 = ids[LSEQ + l];
        float p = pos[(size_t)l * DMODEL + d];
        v0 = emb[(size_t)id0 * DMODEL + d] + p;
        v1 = emb[(size_t)id1 * DMODEL + d] + p;
    }
    t0[threadIdx.y][threadIdx.x] = v0;
    t1[threadIdx.y][threadIdx.x] = v1;
    __syncthreads();
    int l2 = blockIdx.x * 32 + threadIdx.x;
    int d2 = blockIdx.y * 32 + threadIdx.y;
    if (l2 < LSEQ)
        g_x[(size_t)d2 * LSEQ + l2] = make_float2(t0[threadIdx.x][threadIdx.y],
                                                  t1[threadIdx.x][threadIdx.y]);
}

// ---------------- kernel 2: filter spectra (fp16, perm order, pre-conj) ------------
__global__ void __launch_bounds__(TTHR, 2) wspec_kernel(const float* __restrict__ filt_w) {
    extern __shared__ float2 S[];
    const int t = threadIdx.x;
    const int layer = blockIdx.x / (DMODEL / 2);
    const int d0 = (blockIdx.x % (DMODEL / 2)) * 2;
    const int ra = t >> 5, vv = t & 31;
    const bool lo = vv < 16;
    const int baseB = (ra << 9) + vv;
    const float2 waB = g_tw[vv << 4];
    float s32, c32;
    sincospif(-(float)(vv & 15) / 16.0f, &s32, &c32);
    const float2 w32 = make_float2(c32, s32);

    const float* w0p = filt_w + ((size_t)layer * DMODEL + d0) * LSEQ;
    const float* w1p = w0p + LSEQ;

    // pass A: global -> regs -> smem
    {
        float2 v[16];
        #pragma unroll
        for (int j = 0; j < 16; j++) {
            int n = (j << 9) + t;
            v[j] = (n < LSEQ) ? make_float2(w0p[n], w1p[n]) : make_float2(0.f, 0.f);
        }
        dft16_dif(v);
        chain_fwd(v, g_tw[t]);
        #pragma unroll
        for (int r = 0; r < 16; r++) S[AP((r << 9) + t)] = v[br4c(r)];
    }
    __syncthreads();
    passB_fwd(S, baseB, waB, lo, w32);
    __syncthreads();
    // pass C: final DFT-16 over 16 consecutive, store in slot order
    {
        float4* Sv = reinterpret_cast<float4*>(S);
        const int f = 9 * t;
        float2 v[16];
        #pragma unroll
        for (int j = 0; j < 8; j++) {
            float4 q4 = Sv[f + j];
            v[2 * j]     = make_float2(q4.x, q4.y);
            v[2 * j + 1] = make_float2(q4.z, q4.w);
        }
        dft16_dif(v);
        #pragma unroll
        for (int j = 0; j < 8; j++)
            Sv[f + j] = make_float4(v[2 * j].x, v[2 * j].y, v[2 * j + 1].x, v[2 * j + 1].y);
    }
    __syncthreads();
    // unpack packed-real spectra, store fp16 conjugates at position index (coalesced)
    unsigned* out0 = reinterpret_cast<unsigned*>(g_w) + (size_t)(layer * DMODEL + d0) * NFFT;
    unsigned* out1 = out0 + NFFT;
    #pragma unroll
    for (int it = 0; it < 16; it++) {
        int p = t + (it << 9);
        int k = posk(p);
        int kn = (NFFT - k) & (NFFT - 1);
        int pn = kpos(kn);
        float2 Zk = S[AP(p)], Zn = S[AP(pn)];
        out0[p] = f2h2(make_float2(0.5f * (Zk.x + Zn.x), 0.5f * (Zn.y - Zk.y)));
        out1[p] = f2h2(make_float2(0.5f * (Zk.y + Zn.y), 0.5f * (Zk.x - Zn.x)));
    }
}

// ---------------- kernel 3: ALL 12 layers, 5-phase FFT, X resident ----------------
__global__ void __launch_bounds__(TTHR, 2) conv_all_kernel(const float* __restrict__ filt_b) {
    extern __shared__ float2 sh[];
    float2* S = sh;
    float2* X = sh + SPAD;
    const int t = threadIdx.x;
    const int d = blockIdx.x;
    const int ra = t >> 5, vv = t & 31;
    const bool lo = vv < 16;
    const int baseB = (ra << 9) + vv;
    const float2 waA = g_tw[t];
    const float2 cwA = conjf(waA);
    const float2 waB = g_tw[vv << 4];
    const float2 cwB = conjf(waB);
    float s32, c32;
    sincospif(-(float)(vv & 15) / 16.0f, &s32, &c32);
    const float2 w32  = make_float2(c32, s32);
    const float2 cw32 = make_float2(c32, -s32);

    float2* xg = g_x + (size_t)d * LSEQ;
    #pragma unroll
    for (int j = 0; j < 8; j++) {
        int n = (j << 9) + t;
        if (n < LSEQ) X[n] = xg[n];
    }
    __syncthreads();

    for (int layer = 0; layer < NLAYERS; layer++) {
        const float bias = filt_b[layer * DMODEL + d];

        // pass A: X(smem) -> regs -> S
        {
            float2 v[16];
            #pragma unroll
            for (int j = 0; j < 16; j++) {
                int n = (j << 9) + t;
                v[j] = (n < LSEQ) ? X[n] : make_float2(0.f, 0.f);
            }
            dft16_dif(v);
            chain_fwd(v, waA);
            #pragma unroll
            for (int r = 0; r < 16; r++) S[AP((r << 9) + t)] = v[br4c(r)];
        }
        __syncthreads();
        passB_fwd(S, baseB, waB, lo, w32);
        __syncthreads();
        // pass Cf: final DFT-16 + fp16 spectrum multiply + inverse DFT-16, registers only
        {
            const uint4* wrow = g_w + (((size_t)(layer * DMODEL + d)) << 11) + (t << 2);
            uint4 W0 = wrow[0], W1 = wrow[1], W2 = wrow[2], W3 = wrow[3];
            float4* Sv = reinterpret_cast<float4*>(S);
            const int f = 9 * t;
            float2 v[16];
            #pragma unroll
            for (int j = 0; j < 8; j++) {
                float4 q4 = Sv[f + j];
                v[2 * j]     = make_float2(q4.x, q4.y);
                v[2 * j + 1] = make_float2(q4.z, q4.w);
            }
            dft16_dif(v);
            v[0]  = cmul(v[0],  h2f2(W0.x)); v[1]  = cmul(v[1],  h2f2(W0.y));
            v[2]  = cmul(v[2],  h2f2(W0.z)); v[3]  = cmul(v[3],  h2f2(W0.w));
            v[4]  = cmul(v[4],  h2f2(W1.x)); v[5]  = cmul(v[5],  h2f2(W1.y));
            v[6]  = cmul(v[6],  h2f2(W1.z)); v[7]  = cmul(v[7],  h2f2(W1.w));
            v[8]  = cmul(v[8],  h2f2(W2.x)); v[9]  = cmul(v[9],  h2f2(W2.y));
            v[10] = cmul(v[10], h2f2(W2.z)); v[11] = cmul(v[11], h2f2(W2.w));
            v[12] = cmul(v[12], h2f2(W3.x)); v[13] = cmul(v[13], h2f2(W3.y));
            v[14] = cmul(v[14], h2f2(W3.z)); v[15] = cmul(v[15], h2f2(W3.w));
            dft16_dit_conj(v);
            #pragma unroll
            for (int j = 0; j < 8; j++)
                Sv[f + j] = make_float4(v[2 * j].x, v[2 * j].y, v[2 * j + 1].x, v[2 * j + 1].y);
        }
        __syncthreads();
        passB_inv(S, baseB, cwB, lo, cw32);
        __syncthreads();
        // pass A': S -> regs -> residual update of X (packed fma)
        {
            float2 v[16];
            #pragma unroll
            for (int r = 0; r < 16; r++) v[br4c(r)] = S[AP((r << 9) + t)];
            chain_fwd(v, cwA);
            dft16_dit_conj(v);
            const float inv = 1.0f / (float)NFFT;
            const float2 inv2  = make_float2(inv, inv);
            const float2 bias2 = make_float2(bias, bias);
            #pragma unroll
            for (int j = 0; j < 16; j++) {
                int n = (j << 9) + t;
                int to = (n + 2047) & (NFFT - 1);
                if (to < LSEQ) {
                    X[to] = lfma(v[j], inv2, cadd(X[to], bias2));
                }
            }
        }
        __syncthreads();
    }

    #pragma unroll
    for (int j = 0; j < 8; j++) {
        int n = (j << 9) + t;
        if (n < LSEQ) xg[n] = X[n];
    }
}

// ---------------- kernel 4: LayerNorm + projection ----------------
__global__ void __launch_bounds__(1024) final_kernel(const float* __restrict__ ln_g,
                                                     const float* __restrict__ ln_b,
                                                     const float* __restrict__ qa_w,
                                                     const float* __restrict__ qa_b,
                                                     float* __restrict__ out) {
    __shared__ float red[8][32][32];
    const int b  = blockIdx.y;
    const int tx = threadIdx.x, ty = threadIdx.y;
    const int l  = blockIdx.x * 32 + tx;
    const bool valid = (l < LSEQ);

    float S = 0, S2 = 0, A0 = 0, A1 = 0, G0 = 0, G1 = 0, B0 = 0, B1 = 0;
    for (int d = ty; d < DMODEL; d += 32) {
        float2 xv = valid ? g_x[(size_t)d * LSEQ + l] : make_float2(0.f, 0.f);
        float v  = b ? xv.y : xv.x;
        float g  = ln_g[d], bb = ln_b[d];
        float w0 = qa_w[2 * d], w1 = qa_w[2 * d + 1];
        S += v; S2 += v * v;
        float gv = g * v;
        A0 += gv * w0; A1 += gv * w1;
        G0 += g * w0;  G1 += g * w1;
        B0 += bb * w0; B1 += bb * w1;
    }
    red[0][ty][tx] = S;  red[1][ty][tx] = S2;
    red[2][ty][tx] = A0; red[3][ty][tx] = A1;
    red[4][ty][tx] = G0; red[5][ty][tx] = G1;
    red[6][ty][tx] = B0; red[7][ty][tx] = B1;
    __syncthreads();
    for (int s = 16; s > 0; s >>= 1) {
        if (ty < s) {
            #pragma unroll
            for (int a = 0; a < 8; a++) red[a][ty][tx] += red[a][ty + s][tx];
        }
        __syncthreads();
    }
    if (ty == 0 && valid) {
        float Sv = red[0][0][tx], S2v = red[1][0][tx];
        float a0 = red[2][0][tx], a1  = red[3][0][tx];
        float g0 = red[4][0][tx], g1  = red[5][0][tx];
        float b0 = red[6][0][tx], b1  = red[7][0][tx];
        float m   = Sv * (1.0f / DMODEL);
        float var = S2v * (1.0f / DMODEL) - m * m;
        float r   = rsqrtf(var + 1e-5f);
        float o0  = r * (a0 - m * g0) + b0 + qa_b[0];
        float o1  = r * (a1 - m * g1) + b1 + qa_b[1];
        out[b * LSEQ + l]            = o0;
        out[2 * LSEQ + b * LSEQ + l] = o1;
    }
}

// ---------------- host launcher ----------------
extern "C" void kernel_launch(void* const* d_in, const int* in_sizes, int n_in,
                              void* d_out, int out_size) {
    const int*   ids  = (const int*)  d_in[0];
    const float* emb  = (const float*)d_in[1];
    const float* pos  = (const float*)d_in[2];
    const float* fw   = (const float*)d_in[3];
    const float* fb   = (const float*)d_in[4];
    const float* lng  = (const float*)d_in[5];
    const float* lnb  = (const float*)d_in[6];
    const float* qaw  = (const float*)d_in[7];
    const float* qab  = (const float*)d_in[8];
    float* out = (float*)d_out;

    cudaFuncSetAttribute(wspec_kernel,    cudaFuncAttributeMaxDynamicSharedMemorySize, WSPEC_SMEM);
    cudaFuncSetAttribute(conv_all_kernel, cudaFuncAttributeMaxDynamicSharedMemorySize, CONV_SMEM);

    tw_init_kernel<<<1, 512>>>();
    embed_kernel<<<dim3(128, DMODEL / 32), dim3(32, 32)>>>(ids, emb, pos);
    wspec_kernel<<<NLAYERS * (DMODEL / 2), TTHR, WSPEC_SMEM>>>(fw);
    conv_all_kernel<<<DMODEL, TTHR, CONV_SMEM>>>(fb);
    final_kernel<<<dim3(128, 2), dim3(32, 32)>>>(lng, lnb, qaw, qab, out);
}

// round 7
// speedup vs baseline: 1.0378x; 1.0378x over previous
#include <cuda_runtime.h>
#include <cuda_fp16.h>
#include <math.h>

#define NFFT    8192
#define LSEQ    4095
#define DMODEL  768
#define NLAYERS 12
#define TTHR    512
#define SPAD    9216                      // 8192 + 2*(8192/16) padding
#define AP(p)   ((p) + (((p) >> 4) << 1))
#define CONV_SMEM  ((SPAD + 4096) * sizeof(float2))
#define WSPEC_SMEM (SPAD * sizeof(float2))

// ---------------- device scratch ----------------
__device__ float2 g_x[DMODEL * LSEQ];                      // packed {b0,b1}, (D,L)
__device__ uint4  g_w[(size_t)NLAYERS * DMODEL * 2048];    // fp16 spectra, perm order, 302 MB

// ---------------- complex helpers (scalar — R5 proven) ----------------
__device__ __forceinline__ float2 cadd(float2 a, float2 b) { return make_float2(a.x + b.x, a.y + b.y); }
__device__ __forceinline__ float2 csub(float2 a, float2 b) { return make_float2(a.x - b.x, a.y - b.y); }
__device__ __forceinline__ float2 cmul(float2 a, float2 b) {
    return make_float2(fmaf(a.x, b.x, -a.y * b.y), fmaf(a.x, b.y, a.y * b.x));
}
__device__ __forceinline__ float2 cmulf(float2 a, float c, float s) {
    return make_float2(fmaf(a.x, c, -a.y * s), fmaf(a.x, s, a.y * c));
}
__device__ __forceinline__ float2 conjf(float2 a) { return make_float2(a.x, -a.y); }
__device__ __forceinline__ float2 h2f2(unsigned u) {
    __half2 h = *reinterpret_cast<__half2*>(&u);
    return __half22float2(h);
}
__device__ __forceinline__ unsigned f2h2(float2 v) {
    __half2 h = __floats2half2_rn(v.x, v.y);
    return *reinterpret_cast<unsigned*>(&h);
}
// W_8192^k for k >= 0 (negative exponent direction handled by caller sign)
__device__ __forceinline__ float2 wroot(float k) {
    float s, c;
    sincospif(-k / 4096.0f, &s, &c);
    return make_float2(c, s);
}

// 4-bit bit reversal (involution)
__device__ __forceinline__ constexpr int br4c(int r) {
    return ((r & 1) << 3) | ((r & 2) << 1) | ((r & 4) >> 1) | ((r & 8) >> 3);
}
__device__ __forceinline__ int br4(int r) {
    return ((r & 1) << 3) | ((r & 2) << 1) | ((r & 4) >> 1) | ((r & 8) >> 3);
}

// position <-> frequency maps for decomposition 16(512) x 16(32) x 2(16) x 16(1)
__device__ __forceinline__ int posk(int p) {
    return (p >> 9) | (((p >> 5) & 15) << 4) | (((p >> 4) & 1) << 8) | (br4(p & 15) << 9);
}
__device__ __forceinline__ int kpos(int k) {
    return ((k & 15) << 9) | (((k >> 4) & 15) << 5) | (((k >> 8) & 1) << 4) | br4((k >> 9) & 15);
}

// multiply by W16^k (forward) or conj (inverse)
__device__ __forceinline__ float2 twk(float2 a, int k, bool cj) {
    const float c1 = 0.92387953251128675613f;
    const float s1 = 0.38268343236508977173f;
    const float r2 = 0.70710678118654752440f;
    float c, s;
    switch (k & 7) {
        case 0: return a;
        case 1: c =  c1; s = -s1; break;
        case 2: c =  r2; s = -r2; break;
        case 3: c =  s1; s = -c1; break;
        case 4: return cj ? make_float2(-a.y, a.x) : make_float2(a.y, -a.x);
        case 5: c = -s1; s = -c1; break;
        case 6: c = -r2; s = -r2; break;
        default: c = -c1; s = -s1; break;
    }
    if (cj) s = -s;
    return cmulf(a, c, s);
}

// stages 2..4 of the forward DIF DFT16
__device__ __forceinline__ void dft16_dif_tail(float2* v) {
    #pragma unroll
    for (int B = 0; B < 16; B += 8)
        #pragma unroll
        for (int i = 0; i < 4; i++) {
            float2 a = v[B + i], b = v[B + i + 4];
            v[B + i] = cadd(a, b); v[B + i + 4] = twk(csub(a, b), 2 * i, false);
        }
    #pragma unroll
    for (int B = 0; B < 16; B += 4)
        #pragma unroll
        for (int i = 0; i < 2; i++) {
            float2 a = v[B + i], b = v[B + i + 2];
            v[B + i] = cadd(a, b); v[B + i + 2] = twk(csub(a, b), 4 * i, false);
        }
    #pragma unroll
    for (int B = 0; B < 16; B += 2) {
        float2 a = v[B], b = v[B + 1];
        v[B] = cadd(a, b); v[B + 1] = csub(a, b);
    }
}

// forward DIF DFT16: natural input, slot q holds bin br4(q)
__device__ __forceinline__ void dft16_dif(float2* v) {
    #pragma unroll
    for (int i = 0; i < 8; i++) {
        float2 a = v[i], b = v[i + 8];
        v[i] = cadd(a, b); v[i + 8] = twk(csub(a, b), i, false);
    }
    dft16_dif_tail(v);
}

// forward DIF DFT16 with v[8..15] known zero: first stage is twiddle-copy only
__device__ __forceinline__ void dft16_dif_hz(float2* v) {
    #pragma unroll
    for (int i = 0; i < 8; i++) v[i + 8] = twk(v[i], i, false);
    dft16_dif_tail(v);
}

// stages 1..3 of the inverse DIT DFT16 (conj twiddles)
__device__ __forceinline__ void dft16_dit_conj_head(float2* v) {
    #pragma unroll
    for (int B = 0; B < 16; B += 2) {
        float2 a = v[B], b = v[B + 1];
        v[B] = cadd(a, b); v[B + 1] = csub(a, b);
    }
    #pragma unroll
    for (int B = 0; B < 16; B += 4)
        #pragma unroll
        for (int i = 0; i < 2; i++) {
            float2 a = v[B + i], b = twk(v[B + i + 2], 4 * i, true);
            v[B + i] = cadd(a, b); v[B + i + 2] = csub(a, b);
        }
    #pragma unroll
    for (int B = 0; B < 16; B += 8)
        #pragma unroll
        for (int i = 0; i < 4; i++) {
            float2 a = v[B + i], b = twk(v[B + i + 4], 2 * i, true);
            v[B + i] = cadd(a, b); v[B + i + 4] = csub(a, b);
        }
}

// inverse DIT DFT16 with conj twiddles: slot q holds bin br4(q), natural output
__device__ __forceinline__ void dft16_dit_conj(float2* v) {
    dft16_dit_conj_head(v);
    #pragma unroll
    for (int i = 0; i < 8; i++) {
        float2 a = v[i], b = twk(v[i + 8], i, true);
        v[i] = cadd(a, b); v[i + 8] = csub(a, b);
    }
}

// inverse DIT DFT16 producing only natural outputs {0..3, 12..15}
__device__ __forceinline__ void dft16_dit_conj_out8(float2* v) {
    dft16_dit_conj_head(v);
    #pragma unroll
    for (int i = 0; i < 4; i++) v[i] = cadd(v[i], twk(v[i + 8], i, true));
    #pragma unroll
    for (int i = 4; i < 8; i++) v[i + 8] = csub(v[i], twk(v[i + 8], i, true));
}

// apply forward twiddle chain in place (slot br4c(r) gets *wa^r), two chains
__device__ __forceinline__ void chain_fwd(float2* v, float2 wa) {
    float2 w2 = cmul(wa, wa);
    float2 eo = wa, ee = w2;
    v[br4c(1)] = cmul(v[br4c(1)], eo);
    #pragma unroll
    for (int r = 2; r < 16; r += 2) {
        v[br4c(r)] = cmul(v[br4c(r)], ee);
        eo = cmul(eo, w2);
        v[br4c(r + 1)] = cmul(v[br4c(r + 1)], eo);
        ee = cmul(ee, w2);
    }
}

// pass B forward: radix-16 @32 with twiddle + fused radix-2 @16 via shfl
__device__ __forceinline__ void passB_fwd(float2* S, int baseB, float2 waB,
                                          bool lo, float2 w32) {
    float2 v[16];
    #pragma unroll
    for (int j = 0; j < 16; j++) v[j] = S[AP(baseB + (j << 5))];
    dft16_dif(v);
    chain_fwd(v, waB);
    #pragma unroll
    for (int q = 0; q < 16; q++) {
        float2 val = v[q], oth;
        oth.x = __shfl_xor_sync(0xFFFFFFFFu, val.x, 16);
        oth.y = __shfl_xor_sync(0xFFFFFFFFu, val.y, 16);
        float2 sum = cadd(val, oth);
        float2 dif = cmul(csub(oth, val), w32);
        v[q] = lo ? sum : dif;
    }
    #pragma unroll
    for (int r = 0; r < 16; r++) S[AP(baseB + (r << 5))] = v[br4c(r)];
}

// pass B inverse: undo radix-2 @16 (shfl, conj W32), conj twiddle, DIT-16 @32
__device__ __forceinline__ void passB_inv(float2* S, int baseB, float2 cwB,
                                          bool lo, float2 cw32) {
    float2 v[16];
    #pragma unroll
    for (int r = 0; r < 16; r++) v[br4c(r)] = S[AP(baseB + (r << 5))];
    #pragma unroll
    for (int q = 0; q < 16; q++) {
        float2 tmp = lo ? v[q] : cmul(v[q], cw32);
        float2 oth;
        oth.x = __shfl_xor_sync(0xFFFFFFFFu, tmp.x, 16);
        oth.y = __shfl_xor_sync(0xFFFFFFFFu, tmp.y, 16);
        v[q] = lo ? cadd(tmp, oth) : csub(oth, tmp);
    }
    chain_fwd(v, cwB);
    dft16_dit_conj(v);
    #pragma unroll
    for (int j = 0; j < 16; j++) S[AP(baseB + (j << 5))] = v[j];
}

// ---------------- kernel 1: embedding -> g_x packed (D,L) ----------------
__global__ void __launch_bounds__(1024) embed_kernel(const int* __restrict__ ids,
                                                     const float* __restrict__ emb,
                                                     const float* __restrict__ pos) {
    __shared__ float t0[32][33], t1[32][33];
    int l = blockIdx.x * 32 + threadIdx.y;
    int d = blockIdx.y * 32 + threadIdx.x;
    float v0 = 0.f, v1 = 0.f;
    if (l < LSEQ) {
        int id0 = ids[l], id1 = ids[LSEQ + l];
        float p = pos[(size_t)l * DMODEL + d];
        v0 = emb[(size_t)id0 * DMODEL + d] + p;
        v1 = emb[(size_t)id1 * DMODEL + d] + p;
    }
    t0[threadIdx.y][threadIdx.x] = v0;
    t1[threadIdx.y][threadIdx.x] = v1;
    __syncthreads();
    int l2 = blockIdx.x * 32 + threadIdx.x;
    int d2 = blockIdx.y * 32 + threadIdx.y;
    if (l2 < LSEQ)
        g_x[(size_t)d2 * LSEQ + l2] = make_float2(t0[threadIdx.x][threadIdx.y],
                                                  t1[threadIdx.x][threadIdx.y]);
}

// ---------------- kernel 2: filter spectra (fp16, perm order, pre-conj) ------------
__global__ void __launch_bounds__(TTHR, 2) wspec_kernel(const float* __restrict__ filt_w) {
    extern __shared__ float2 S[];
    const int t = threadIdx.x;
    const int layer = blockIdx.x / (DMODEL / 2);
    const int d0 = (blockIdx.x % (DMODEL / 2)) * 2;
    const int ra = t >> 5, vv = t & 31;
    const bool lo = vv < 16;
    const int baseB = (ra << 9) + vv;
    const float2 waB = wroot((float)(vv << 4));
    float s32, c32;
    sincospif(-(float)(vv & 15) / 16.0f, &s32, &c32);
    const float2 w32 = make_float2(c32, s32);

    const float* w0p = filt_w + ((size_t)layer * DMODEL + d0) * LSEQ;
    const float* w1p = w0p + LSEQ;

    // pass A: global -> regs -> smem (top half of input always zero)
    {
        float2 v[16];
        #pragma unroll
        for (int j = 0; j < 8; j++) {
            int n = (j << 9) + t;
            v[j] = (n < LSEQ) ? make_float2(w0p[n], w1p[n]) : make_float2(0.f, 0.f);
        }
        dft16_dif_hz(v);
        chain_fwd(v, wroot((float)t));
        #pragma unroll
        for (int r = 0; r < 16; r++) S[AP((r << 9) + t)] = v[br4c(r)];
    }
    __syncthreads();
    passB_fwd(S, baseB, waB, lo, w32);
    __syncthreads();
    // pass C: final DFT-16 over 16 consecutive, store in slot order
    {
        float4* Sv = reinterpret_cast<float4*>(S);
        const int f = 9 * t;
        float2 v[16];
        #pragma unroll
        for (int j = 0; j < 8; j++) {
            float4 q4 = Sv[f + j];
            v[2 * j]     = make_float2(q4.x, q4.y);
            v[2 * j + 1] = make_float2(q4.z, q4.w);
        }
        dft16_dif(v);
        #pragma unroll
        for (int j = 0; j < 8; j++)
            Sv[f + j] = make_float4(v[2 * j].x, v[2 * j].y, v[2 * j + 1].x, v[2 * j + 1].y);
    }
    __syncthreads();
    // unpack packed-real spectra, store fp16 conjugates at position index (coalesced)
    unsigned* out0 = reinterpret_cast<unsigned*>(g_w) + (size_t)(layer * DMODEL + d0) * NFFT;
    unsigned* out1 = out0 + NFFT;
    #pragma unroll
    for (int it = 0; it < 16; it++) {
        int p = t + (it << 9);
        int k = posk(p);
        int kn = (NFFT - k) & (NFFT - 1);
        int pn = kpos(kn);
        float2 Zk = S[AP(p)], Zn = S[AP(pn)];
        out0[p] = f2h2(make_float2(0.5f * (Zk.x + Zn.x), 0.5f * (Zn.y - Zk.y)));
        out1[p] = f2h2(make_float2(0.5f * (Zk.y + Zn.y), 0.5f * (Zk.x - Zn.x)));
    }
}

// ---------------- kernel 3: ALL 12 layers, 5-phase FFT, X resident ----------------
__global__ void __launch_bounds__(TTHR, 2) conv_all_kernel(const float* __restrict__ filt_b) {
    extern __shared__ float2 sh[];
    float2* S = sh;
    float2* X = sh + SPAD;
    const int t = threadIdx.x;
    const int d = blockIdx.x;
    const int ra = t >> 5, vv = t & 31;
    const bool lo = vv < 16;
    const int baseB = (ra << 9) + vv;
    const float2 waA = wroot((float)t);
    const float2 cwA = conjf(waA);
    const float2 waB = wroot((float)(vv << 4));
    const float2 cwB = conjf(waB);
    float s32, c32;
    sincospif(-(float)(vv & 15) / 16.0f, &s32, &c32);
    const float2 w32  = make_float2(c32, s32);
    const float2 cw32 = make_float2(c32, -s32);

    float2* xg = g_x + (size_t)d * LSEQ;
    #pragma unroll
    for (int j = 0; j < 8; j++) {
        int n = (j << 9) + t;
        if (n < LSEQ) X[n] = xg[n];
    }
    __syncthreads();

    for (int layer = 0; layer < NLAYERS; layer++) {
        const float bias = filt_b[layer * DMODEL + d];

        // pass A: X(smem) -> regs -> S (top half of input always zero)
        {
            float2 v[16];
            #pragma unroll
            for (int j = 0; j < 8; j++) {
                int n = (j << 9) + t;
                v[j] = (n < LSEQ) ? X[n] : make_float2(0.f, 0.f);
            }
            dft16_dif_hz(v);
            chain_fwd(v, waA);
            #pragma unroll
            for (int r = 0; r < 16; r++) S[AP((r << 9) + t)] = v[br4c(r)];
        }
        __syncthreads();
        passB_fwd(S, baseB, waB, lo, w32);
        __syncthreads();
        // pass Cf: final DFT-16 + fp16 spectrum multiply + inverse DFT-16, registers only
        {
            const uint4* wrow = g_w + (((size_t)(layer * DMODEL + d)) << 11) + (t << 2);
            uint4 W0 = wrow[0], W1 = wrow[1], W2 = wrow[2], W3 = wrow[3];
            float4* Sv = reinterpret_cast<float4*>(S);
            const int f = 9 * t;
            float2 v[16];
            #pragma unroll
            for (int j = 0; j < 8; j++) {
                float4 q4 = Sv[f + j];
                v[2 * j]     = make_float2(q4.x, q4.y);
                v[2 * j + 1] = make_float2(q4.z, q4.w);
            }
            dft16_dif(v);
            v[0]  = cmul(v[0],  h2f2(W0.x)); v[1]  = cmul(v[1],  h2f2(W0.y));
            v[2]  = cmul(v[2],  h2f2(W0.z)); v[3]  = cmul(v[3],  h2f2(W0.w));
            v[4]  = cmul(v[4],  h2f2(W1.x)); v[5]  = cmul(v[5],  h2f2(W1.y));
            v[6]  = cmul(v[6],  h2f2(W1.z)); v[7]  = cmul(v[7],  h2f2(W1.w));
            v[8]  = cmul(v[8],  h2f2(W2.x)); v[9]  = cmul(v[9],  h2f2(W2.y));
            v[10] = cmul(v[10], h2f2(W2.z)); v[11] = cmul(v[11], h2f2(W2.w));
            v[12] = cmul(v[12], h2f2(W3.x)); v[13] = cmul(v[13], h2f2(W3.y));
            v[14] = cmul(v[14], h2f2(W3.z)); v[15] = cmul(v[15], h2f2(W3.w));
            dft16_dit_conj(v);
            #pragma unroll
            for (int j = 0; j < 8; j++)
                Sv[f + j] = make_float4(v[2 * j].x, v[2 * j].y, v[2 * j + 1].x, v[2 * j + 1].y);
        }
        __syncthreads();
        passB_inv(S, baseB, cwB, lo, cw32);
        __syncthreads();
        // pass A': S -> regs -> residual update of X (only 8 of 16 outputs land in [0,L))
        {
            float2 v[16];
            #pragma unroll
            for (int r = 0; r < 16; r++) v[br4c(r)] = S[AP((r << 9) + t)];
            chain_fwd(v, cwA);
            dft16_dit_conj_out8(v);
            const float inv = 1.0f / (float)NFFT;
            // j = 0..3: to = (j<<9) + t + 2047, always < LSEQ
            #pragma unroll
            for (int j = 0; j < 4; j++) {
                int to = (j << 9) + t + 2047;
                float2 old = X[to];
                X[to] = make_float2(fmaf(v[j].x, inv, old.x + bias),
                                    fmaf(v[j].y, inv, old.y + bias));
            }
            // j = 12..15: to = (j<<9) + t - 6145; j==12 requires t >= 1
            #pragma unroll
            for (int j = 12; j < 16; j++) {
                int to = (j << 9) + t - 6145;
                if (j > 12 || t >= 1) {
                    float2 old = X[to];
                    X[to] = make_float2(fmaf(v[j].x, inv, old.x + bias),
                                        fmaf(v[j].y, inv, old.y + bias));
                }
            }
        }
        __syncthreads();
    }

    #pragma unroll
    for (int j = 0; j < 8; j++) {
        int n = (j << 9) + t;
        if (n < LSEQ) xg[n] = X[n];
    }
}

// ---------------- kernel 4: LayerNorm + projection ----------------
__global__ void __launch_bounds__(1024) final_kernel(const float* __restrict__ ln_g,
                                                     const float* __restrict__ ln_b,
                                                     const float* __restrict__ qa_w,
                                                     const float* __restrict__ qa_b,
                                                     float* __restrict__ out) {
    __shared__ float red[8][32][32];
    const int b  = blockIdx.y;
    const int tx = threadIdx.x, ty = threadIdx.y;
    const int l  = blockIdx.x * 32 + tx;
    const bool valid = (l < LSEQ);

    float S = 0, S2 = 0, A0 = 0, A1 = 0, G0 = 0, G1 = 0, B0 = 0, B1 = 0;
    for (int d = ty; d < DMODEL; d += 32) {
        float2 xv = valid ? g_x[(size_t)d * LSEQ + l] : make_float2(0.f, 0.f);
        float v  = b ? xv.y : xv.x;
        float g  = ln_g[d], bb = ln_b[d];
        float w0 = qa_w[2 * d], w1 = qa_w[2 * d + 1];
        S += v; S2 += v * v;
        float gv = g * v;
        A0 += gv * w0; A1 += gv * w1;
        G0 += g * w0;  G1 += g * w1;
        B0 += bb * w0; B1 += bb * w1;
    }
    red[0][ty][tx] = S;  red[1][ty][tx] = S2;
    red[2][ty][tx] = A0; red[3][ty][tx] = A1;
    red[4][ty][tx] = G0; red[5][ty][tx] = G1;
    red[6][ty][tx] = B0; red[7][ty][tx] = B1;
    __syncthreads();
    for (int s = 16; s > 0; s >>= 1) {
        if (ty < s) {
            #pragma unroll
            for (int a = 0; a < 8; a++) red[a][ty][tx] += red[a][ty + s][tx];
        }
        __syncthreads();
    }
    if (ty == 0 && valid) {
        float Sv = red[0][0][tx], S2v = red[1][0][tx];
        float a0 = red[2][0][tx], a1  = red[3][0][tx];
        float g0 = red[4][0][tx], g1  = red[5][0][tx];
        float b0 = red[6][0][tx], b1  = red[7][0][tx];
        float m   = Sv * (1.0f / DMODEL);
        float var = S2v * (1.0f / DMODEL) - m * m;
        float r   = rsqrtf(var + 1e-5f);
        float o0  = r * (a0 - m * g0) + b0 + qa_b[0];
        float o1  = r * (a1 - m * g1) + b1 + qa_b[1];
        out[b * LSEQ + l]            = o0;
        out[2 * LSEQ + b * LSEQ + l] = o1;
    }
}

// ---------------- host launcher ----------------
extern "C" void kernel_launch(void* const* d_in, const int* in_sizes, int n_in,
                              void* d_out, int out_size) {
    const int*   ids  = (const int*)  d_in[0];
    const float* emb  = (const float*)d_in[1];
    const float* pos  = (const float*)d_in[2];
    const float* fw   = (const float*)d_in[3];
    const float* fb   = (const float*)d_in[4];
    const float* lng  = (const float*)d_in[5];
    const float* lnb  = (const float*)d_in[6];
    const float* qaw  = (const float*)d_in[7];
    const float* qab  = (const float*)d_in[8];
    float* out = (float*)d_out;

    cudaFuncSetAttribute(wspec_kernel,    cudaFuncAttributeMaxDynamicSharedMemorySize, WSPEC_SMEM);
    cudaFuncSetAttribute(conv_all_kernel, cudaFuncAttributeMaxDynamicSharedMemorySize, CONV_SMEM);

    embed_kernel<<<dim3(128, DMODEL / 32), dim3(32, 32)>>>(ids, emb, pos);
    wspec_kernel<<<NLAYERS * (DMODEL / 2), TTHR, WSPEC_SMEM>>>(fw);
    conv_all_kernel<<<DMODEL, TTHR, CONV_SMEM>>>(fb);
    final_kernel<<<dim3(128, 2), dim3(32, 32)>>>(lng, lnb, qaw, qab, out);
}

// round 8
// speedup vs baseline: 1.1254x; 1.0844x over previous
#include <cuda_runtime.h>
#include <cuda_fp16.h>
#include <math.h>

#define NFFT    8192
#define LSEQ    4095
#define DMODEL  768
#define NLAYERS 12
#define TTHR    512
#define SPAD    9216                      // 8192 + 2*(8192/16) padding
#define AP(p)   ((p) + (((p) >> 4) << 1))
#define TBL     1040                      // 512 B-twiddles + 512 A-anchors + 16 W32
#define CONV_SMEM  ((SPAD + TBL) * sizeof(float2))
#define WSPEC_SMEM (SPAD * sizeof(float2))

// ---------------- device scratch ----------------
__device__ float2 g_x[DMODEL * LSEQ];                      // packed {b0,b1}, (D,L)
__device__ uint4  g_w[(size_t)NLAYERS * DMODEL * 2048];    // fp16 spectra (pre-shifted, pre-conj), 302 MB

// ---------------- complex helpers ----------------
__device__ __forceinline__ float2 cadd(float2 a, float2 b) { return make_float2(a.x + b.x, a.y + b.y); }
__device__ __forceinline__ float2 csub(float2 a, float2 b) { return make_float2(a.x - b.x, a.y - b.y); }
__device__ __forceinline__ float2 cmul(float2 a, float2 b) {
    return make_float2(fmaf(a.x, b.x, -a.y * b.y), fmaf(a.x, b.y, a.y * b.x));
}
__device__ __forceinline__ float2 cmulf(float2 a, float c, float s) {
    return make_float2(fmaf(a.x, c, -a.y * s), fmaf(a.x, s, a.y * c));
}
__device__ __forceinline__ float2 conjf(float2 a) { return make_float2(a.x, -a.y); }
__device__ __forceinline__ float2 h2f2(unsigned u) {
    __half2 h = *reinterpret_cast<__half2*>(&u);
    return __half22float2(h);
}
__device__ __forceinline__ unsigned f2h2(float2 v) {
    __half2 h = __floats2half2_rn(v.x, v.y);
    return *reinterpret_cast<unsigned*>(&h);
}
// W_8192^m from integer m (exact reduction, no float-angle loss)
__device__ __forceinline__ float2 wrootm(int m) {
    float s, c;
    sincospif(-(float)(m & 8191) / 4096.0f, &s, &c);
    return make_float2(c, s);
}

// 4-bit bit reversal (involution)
__device__ __forceinline__ constexpr int br4c(int r) {
    return ((r & 1) << 3) | ((r & 2) << 1) | ((r & 4) >> 1) | ((r & 8) >> 3);
}
__device__ __forceinline__ int br4(int r) {
    return ((r & 1) << 3) | ((r & 2) << 1) | ((r & 4) >> 1) | ((r & 8) >> 3);
}

// position <-> frequency maps for decomposition 16(512) x 16(32) x 2(16) x 16(1)
__device__ __forceinline__ int posk(int p) {
    return (p >> 9) | (((p >> 5) & 15) << 4) | (((p >> 4) & 1) << 8) | (br4(p & 15) << 9);
}
__device__ __forceinline__ int kpos(int k) {
    return ((k & 15) << 9) | (((k >> 4) & 15) << 5) | (((k >> 8) & 1) << 4) | br4((k >> 9) & 15);
}

// multiply by W16^k (forward) or conj (inverse)
__device__ __forceinline__ float2 twk(float2 a, int k, bool cj) {
    const float c1 = 0.92387953251128675613f;
    const float s1 = 0.38268343236508977173f;
    const float r2 = 0.70710678118654752440f;
    float c, s;
    switch (k & 7) {
        case 0: return a;
        case 1: c =  c1; s = -s1; break;
        case 2: c =  r2; s = -r2; break;
        case 3: c =  s1; s = -c1; break;
        case 4: return cj ? make_float2(-a.y, a.x) : make_float2(a.y, -a.x);
        case 5: c = -s1; s = -c1; break;
        case 6: c = -r2; s = -r2; break;
        default: c = -c1; s = -s1; break;
    }
    if (cj) s = -s;
    return cmulf(a, c, s);
}

// stages 2..4 of the forward DIF DFT16
__device__ __forceinline__ void dft16_dif_tail(float2* v) {
    #pragma unroll
    for (int B = 0; B < 16; B += 8)
        #pragma unroll
        for (int i = 0; i < 4; i++) {
            float2 a = v[B + i], b = v[B + i + 4];
            v[B + i] = cadd(a, b); v[B + i + 4] = twk(csub(a, b), 2 * i, false);
        }
    #pragma unroll
    for (int B = 0; B < 16; B += 4)
        #pragma unroll
        for (int i = 0; i < 2; i++) {
            float2 a = v[B + i], b = v[B + i + 2];
            v[B + i] = cadd(a, b); v[B + i + 2] = twk(csub(a, b), 4 * i, false);
        }
    #pragma unroll
    for (int B = 0; B < 16; B += 2) {
        float2 a = v[B], b = v[B + 1];
        v[B] = cadd(a, b); v[B + 1] = csub(a, b);
    }
}

// forward DIF DFT16: natural input, slot q holds bin br4(q)
__device__ __forceinline__ void dft16_dif(float2* v) {
    #pragma unroll
    for (int i = 0; i < 8; i++) {
        float2 a = v[i], b = v[i + 8];
        v[i] = cadd(a, b); v[i + 8] = twk(csub(a, b), i, false);
    }
    dft16_dif_tail(v);
}

// forward DIF DFT16 with v[8..15] known zero
__device__ __forceinline__ void dft16_dif_hz(float2* v) {
    #pragma unroll
    for (int i = 0; i < 8; i++) v[i + 8] = twk(v[i], i, false);
    dft16_dif_tail(v);
}

// stages 1..3 of the inverse DIT DFT16 (conj twiddles)
__device__ __forceinline__ void dft16_dit_conj_head(float2* v) {
    #pragma unroll
    for (int B = 0; B < 16; B += 2) {
        float2 a = v[B], b = v[B + 1];
        v[B] = cadd(a, b); v[B + 1] = csub(a, b);
    }
    #pragma unroll
    for (int B = 0; B < 16; B += 4)
        #pragma unroll
        for (int i = 0; i < 2; i++) {
            float2 a = v[B + i], b = twk(v[B + i + 2], 4 * i, true);
            v[B + i] = cadd(a, b); v[B + i + 2] = csub(a, b);
        }
    #pragma unroll
    for (int B = 0; B < 16; B += 8)
        #pragma unroll
        for (int i = 0; i < 4; i++) {
            float2 a = v[B + i], b = twk(v[B + i + 4], 2 * i, true);
            v[B + i] = cadd(a, b); v[B + i + 4] = csub(a, b);
        }
}

// inverse DIT DFT16 with conj twiddles: full natural output
__device__ __forceinline__ void dft16_dit_conj(float2* v) {
    dft16_dit_conj_head(v);
    #pragma unroll
    for (int i = 0; i < 8; i++) {
        float2 a = v[i], b = twk(v[i + 8], i, true);
        v[i] = cadd(a, b); v[i + 8] = csub(a, b);
    }
}

// inverse DIT DFT16 producing only natural outputs 0..7 (sum side)
__device__ __forceinline__ void dft16_dit_conj_low8(float2* v) {
    dft16_dit_conj_head(v);
    #pragma unroll
    for (int i = 0; i < 8; i++) v[i] = cadd(v[i], twk(v[i + 8], i, true));
}

// apply forward twiddle chain in place (slot br4c(r) gets *wa^r), two chains
__device__ __forceinline__ void chain_fwd(float2* v, float2 wa) {
    float2 w2 = cmul(wa, wa);
    float2 eo = wa, ee = w2;
    v[br4c(1)] = cmul(v[br4c(1)], eo);
    #pragma unroll
    for (int r = 2; r < 16; r += 2) {
        v[br4c(r)] = cmul(v[br4c(r)], ee);
        eo = cmul(eo, w2);
        v[br4c(r + 1)] = cmul(v[br4c(r + 1)], eo);
        ee = cmul(ee, w2);
    }
}

// pass B forward with smem twiddle table T (conv kernel)
__device__ __forceinline__ void passB_fwd_tbl(float2* S, const float2* T, int baseB,
                                              int vv, bool lo) {
    float2 v[16];
    #pragma unroll
    for (int j = 0; j < 16; j++) v[j] = S[AP(baseB + (j << 5))];
    dft16_dif(v);
    #pragma unroll
    for (int r = 1; r < 16; r++) v[br4c(r)] = cmul(v[br4c(r)], T[(r << 5) + vv]);
    float2 w32 = T[1024 + (vv & 15)];
    #pragma unroll
    for (int q = 0; q < 16; q++) {
        float2 val = v[q], oth;
        oth.x = __shfl_xor_sync(0xFFFFFFFFu, val.x, 16);
        oth.y = __shfl_xor_sync(0xFFFFFFFFu, val.y, 16);
        float2 sum = cadd(val, oth);
        float2 dif = cmul(csub(oth, val), w32);
        v[q] = lo ? sum : dif;
    }
    #pragma unroll
    for (int r = 0; r < 16; r++) S[AP(baseB + (r << 5))] = v[br4c(r)];
}

// pass B inverse with smem twiddle table (conj applied on the fly)
__device__ __forceinline__ void passB_inv_tbl(float2* S, const float2* T, int baseB,
                                              int vv, bool lo) {
    float2 v[16];
    #pragma unroll
    for (int r = 0; r < 16; r++) v[br4c(r)] = S[AP(baseB + (r << 5))];
    float2 w32 = T[1024 + (vv & 15)];
    #pragma unroll
    for (int q = 0; q < 16; q++) {
        float2 tmp = lo ? v[q] : cmulf(v[q], w32.x, -w32.y);
        float2 oth;
        oth.x = __shfl_xor_sync(0xFFFFFFFFu, tmp.x, 16);
        oth.y = __shfl_xor_sync(0xFFFFFFFFu, tmp.y, 16);
        v[q] = lo ? cadd(tmp, oth) : csub(oth, tmp);
    }
    #pragma unroll
    for (int r = 1; r < 16; r++) {
        float2 tw = T[(r << 5) + vv];
        v[br4c(r)] = cmulf(v[br4c(r)], tw.x, -tw.y);
    }
    dft16_dit_conj(v);
    #pragma unroll
    for (int j = 0; j < 16; j++) S[AP(baseB + (j << 5))] = v[j];
}

// ---------------- kernel 1: embedding -> g_x packed (D,L) ----------------
__global__ void __launch_bounds__(1024) embed_kernel(const int* __restrict__ ids,
                                                     const float* __restrict__ emb,
                                                     const float* __restrict__ pos) {
    __shared__ float t0[32][33], t1[32][33];
    int l = blockIdx.x * 32 + threadIdx.y;
    int d = blockIdx.y * 32 + threadIdx.x;
    float v0 = 0.f, v1 = 0.f;
    if (l < LSEQ) {
        int id0 = ids[l], id1 = ids[LSEQ + l];
        float p = pos[(size_t)l * DMODEL + d];
        v0 = emb[(size_t)id0 * DMODEL + d] + p;
        v1 = emb[(size_t)id1 * DMODEL + d] + p;
    }
    t0[threadIdx.y][threadIdx.x] = v0;
    t1[threadIdx.y][threadIdx.x] = v1;
    __syncthreads();
    int l2 = blockIdx.x * 32 + threadIdx.x;
    int d2 = blockIdx.y * 32 + threadIdx.y;
    if (l2 < LSEQ)
        g_x[(size_t)d2 * LSEQ + l2] = make_float2(t0[threadIdx.x][threadIdx.y],
                                                  t1[threadIdx.x][threadIdx.y]);
}

// ---------------- kernel 2: filter spectra (fp16, pre-shifted by 2047, pre-conj) ---
__global__ void __launch_bounds__(TTHR, 2) wspec_kernel(const float* __restrict__ filt_w) {
    extern __shared__ float2 S[];
    const int t = threadIdx.x;
    const int layer = blockIdx.x / (DMODEL / 2);
    const int d0 = (blockIdx.x % (DMODEL / 2)) * 2;
    const int ra = t >> 5, vv = t & 31;
    const bool lo = vv < 16;
    const int baseB = (ra << 9) + vv;
    const float2 waB = wrootm(vv << 4);
    const float2 w32 = wrootm((vv & 15) << 8);

    const float* w0p = filt_w + ((size_t)layer * DMODEL + d0) * LSEQ;
    const float* w1p = w0p + LSEQ;

    // pass A: global -> regs -> smem (top half of input always zero)
    {
        float2 v[16];
        #pragma unroll
        for (int j = 0; j < 8; j++) {
            int n = (j << 9) + t;
            v[j] = (n < LSEQ) ? make_float2(w0p[n], w1p[n]) : make_float2(0.f, 0.f);
        }
        dft16_dif_hz(v);
        chain_fwd(v, wrootm(t));
        #pragma unroll
        for (int r = 0; r < 16; r++) S[AP((r << 9) + t)] = v[br4c(r)];
    }
    __syncthreads();
    // pass B: radix-16 @32 + fused radix-2 @16 via shfl (register twiddle chain)
    {
        float2 v[16];
        #pragma unroll
        for (int j = 0; j < 16; j++) v[j] = S[AP(baseB + (j << 5))];
        dft16_dif(v);
        chain_fwd(v, waB);
        #pragma unroll
        for (int q = 0; q < 16; q++) {
            float2 val = v[q], oth;
            oth.x = __shfl_xor_sync(0xFFFFFFFFu, val.x, 16);
            oth.y = __shfl_xor_sync(0xFFFFFFFFu, val.y, 16);
            float2 sum = cadd(val, oth);
            float2 dif = cmul(csub(oth, val), w32);
            v[q] = lo ? sum : dif;
        }
        #pragma unroll
        for (int r = 0; r < 16; r++) S[AP(baseB + (r << 5))] = v[br4c(r)];
    }
    __syncthreads();
    // pass C: final DFT-16 over 16 consecutive, store in slot order
    {
        float4* Sv = reinterpret_cast<float4*>(S);
        const int f = 9 * t;
        float2 v[16];
        #pragma unroll
        for (int j = 0; j < 8; j++) {
            float4 q4 = Sv[f + j];
            v[2 * j]     = make_float2(q4.x, q4.y);
            v[2 * j + 1] = make_float2(q4.z, q4.w);
        }
        dft16_dif(v);
        #pragma unroll
        for (int j = 0; j < 8; j++)
            Sv[f + j] = make_float4(v[2 * j].x, v[2 * j].y, v[2 * j + 1].x, v[2 * j + 1].y);
    }
    __syncthreads();
    // unpack packed-real spectra; apply circular pre-shift phase; store fp16 conjugates
    unsigned* out0 = reinterpret_cast<unsigned*>(g_w) + (size_t)(layer * DMODEL + d0) * NFFT;
    unsigned* out1 = out0 + NFFT;
    #pragma unroll
    for (int it = 0; it < 16; it++) {
        int p = t + (it << 9);
        int k = posk(p);
        int kn = (NFFT - k) & (NFFT - 1);
        int pn = kpos(kn);
        float2 Zk = S[AP(p)], Zn = S[AP(pn)];
        float2 c00 = make_float2(0.5f * (Zk.x + Zn.x), 0.5f * (Zn.y - Zk.y));
        float2 c10 = make_float2(0.5f * (Zk.y + Zn.y), 0.5f * (Zk.x - Zn.x));
        float2 ph = wrootm(2047 * k);   // delay-by-2047 phase, exact integer reduction
        out0[p] = f2h2(cmul(c00, ph));
        out1[p] = f2h2(cmul(c10, ph));
    }
}

// ---------------- kernel 3: ALL 12 layers, X in registers, 4-phase smem ----------
__global__ void __launch_bounds__(TTHR, 2) conv_all_kernel(const float* __restrict__ filt_b) {
    extern __shared__ float2 sh[];
    float2* S = sh;
    float2* T = sh + SPAD;                // 1040-entry twiddle table
    const int t = threadIdx.x;
    const int d = blockIdx.x;
    const int ra = t >> 5, vv = t & 31;
    const bool lo = vv < 16;
    const int baseB = (ra << 9) + vv;

    // build twiddle tables
    T[t]       = wrootm(((t >> 5) * (t & 31)) << 4);   // B: W^(r*(vv<<4)), idx (r<<5)+vv
    T[512 + t] = wrootm(t);                            // A anchors W^t
    if (t < 16) T[1024 + t] = wrootm(t << 8);          // W_32^i

    // residual accumulator in registers: X[j] = x[(j<<9)+t]
    float2 X[8];
    float2* xg = g_x + (size_t)d * LSEQ;
    #pragma unroll
    for (int j = 0; j < 8; j++) {
        int n = (j << 9) + t;
        X[j] = (n < LSEQ) ? xg[n] : make_float2(0.f, 0.f);
    }
    __syncthreads();

    for (int layer = 0; layer < NLAYERS; layer++) {
        const float bias = filt_b[layer * DMODEL + d];

        // pass A: X(regs) -> S (thread-private slots; safe vs prior A' reads)
        {
            float2 v[16];
            #pragma unroll
            for (int j = 0; j < 8; j++) v[j] = X[j];
            dft16_dif_hz(v);
            chain_fwd(v, T[512 + t]);
            #pragma unroll
            for (int r = 0; r < 16; r++) S[AP((r << 9) + t)] = v[br4c(r)];
        }
        __syncthreads();
        passB_fwd_tbl(S, T, baseB, vv, lo);
        __syncthreads();
        // pass Cf: final DFT-16 + fp16 spectrum multiply + inverse DFT-16
        {
            const uint4* wrow = g_w + (((size_t)(layer * DMODEL + d)) << 11) + (t << 2);
            uint4 W0 = wrow[0], W1 = wrow[1], W2 = wrow[2], W3 = wrow[3];
            float4* Sv = reinterpret_cast<float4*>(S);
            const int f = 9 * t;
            float2 v[16];
            #pragma unroll
            for (int j = 0; j < 8; j++) {
                float4 q4 = Sv[f + j];
                v[2 * j]     = make_float2(q4.x, q4.y);
                v[2 * j + 1] = make_float2(q4.z, q4.w);
            }
            dft16_dif(v);
            v[0]  = cmul(v[0],  h2f2(W0.x)); v[1]  = cmul(v[1],  h2f2(W0.y));
            v[2]  = cmul(v[2],  h2f2(W0.z)); v[3]  = cmul(v[3],  h2f2(W0.w));
            v[4]  = cmul(v[4],  h2f2(W1.x)); v[5]  = cmul(v[5],  h2f2(W1.y));
            v[6]  = cmul(v[6],  h2f2(W1.z)); v[7]  = cmul(v[7],  h2f2(W1.w));
            v[8]  = cmul(v[8],  h2f2(W2.x)); v[9]  = cmul(v[9],  h2f2(W2.y));
            v[10] = cmul(v[10], h2f2(W2.z)); v[11] = cmul(v[11], h2f2(W2.w));
            v[12] = cmul(v[12], h2f2(W3.x)); v[13] = cmul(v[13], h2f2(W3.y));
            v[14] = cmul(v[14], h2f2(W3.z)); v[15] = cmul(v[15], h2f2(W3.w));
            dft16_dit_conj(v);
            #pragma unroll
            for (int j = 0; j < 8; j++)
                Sv[f + j] = make_float4(v[2 * j].x, v[2 * j].y, v[2 * j + 1].x, v[2 * j + 1].y);
        }
        __syncthreads();
        passB_inv_tbl(S, T, baseB, vv, lo);
        __syncthreads();
        // pass A': S -> regs -> residual update of X (outputs land at own slots j=0..7)
        {
            float2 v[16];
            #pragma unroll
            for (int r = 0; r < 16; r++) v[br4c(r)] = S[AP((r << 9) + t)];
            chain_fwd(v, conjf(T[512 + t]));
            dft16_dit_conj_low8(v);
            const float inv = 1.0f / (float)NFFT;
            #pragma unroll
            for (int j = 0; j < 8; j++) {
                if (j < 7 || t < 511) {
                    X[j].x = fmaf(v[j].x, inv, X[j].x + bias);
                    X[j].y = fmaf(v[j].y, inv, X[j].y + bias);
                }
            }
        }
        // no sync: next pass A writes only this thread's own S slots
    }

    #pragma unroll
    for (int j = 0; j < 8; j++) {
        int n = (j << 9) + t;
        if (n < LSEQ) xg[n] = X[j];
    }
}

// ---------------- kernel 4: LayerNorm + projection ----------------
__global__ void __launch_bounds__(1024) final_kernel(const float* __restrict__ ln_g,
                                                     const float* __restrict__ ln_b,
                                                     const float* __restrict__ qa_w,
                                                     const float* __restrict__ qa_b,
                                                     float* __restrict__ out) {
    __shared__ float red[8][32][32];
    const int b  = blockIdx.y;
    const int tx = threadIdx.x, ty = threadIdx.y;
    const int l  = blockIdx.x * 32 + tx;
    const bool valid = (l < LSEQ);

    float S = 0, S2 = 0, A0 = 0, A1 = 0, G0 = 0, G1 = 0, B0 = 0, B1 = 0;
    for (int d = ty; d < DMODEL; d += 32) {
        float2 xv = valid ? g_x[(size_t)d * LSEQ + l] : make_float2(0.f, 0.f);
        float v  = b ? xv.y : xv.x;
        float g  = ln_g[d], bb = ln_b[d];
        float w0 = qa_w[2 * d], w1 = qa_w[2 * d + 1];
        S += v; S2 += v * v;
        float gv = g * v;
        A0 += gv * w0; A1 += gv * w1;
        G0 += g * w0;  G1 += g * w1;
        B0 += bb * w0; B1 += bb * w1;
    }
    red[0][ty][tx] = S;  red[1][ty][tx] = S2;
    red[2][ty][tx] = A0; red[3][ty][tx] = A1;
    red[4][ty][tx] = G0; red[5][ty][tx] = G1;
    red[6][ty][tx] = B0; red[7][ty][tx] = B1;
    __syncthreads();
    for (int s = 16; s > 0; s >>= 1) {
        if (ty < s) {
            #pragma unroll
            for (int a = 0; a < 8; a++) red[a][ty][tx] += red[a][ty + s][tx];
        }
        __syncthreads();
    }
    if (ty == 0 && valid) {
        float Sv = red[0][0][tx], S2v = red[1][0][tx];
        float a0 = red[2][0][tx], a1  = red[3][0][tx];
        float g0 = red[4][0][tx], g1  = red[5][0][tx];
        float b0 = red[6][0][tx], b1  = red[7][0][tx];
        float m   = Sv * (1.0f / DMODEL);
        float var = S2v * (1.0f / DMODEL) - m * m;
        float r   = rsqrtf(var + 1e-5f);
        float o0  = r * (a0 - m * g0) + b0 + qa_b[0];
        float o1  = r * (a1 - m * g1) + b1 + qa_b[1];
        out[b * LSEQ + l]            = o0;
        out[2 * LSEQ + b * LSEQ + l] = o1;
    }
}

// ---------------- host launcher ----------------
extern "C" void kernel_launch(void* const* d_in, const int* in_sizes, int n_in,
                              void* d_out, int out_size) {
    const int*   ids  = (const int*)  d_in[0];
    const float* emb  = (const float*)d_in[1];
    const float* pos  = (const float*)d_in[2];
    const float* fw   = (const float*)d_in[3];
    const float* fb   = (const float*)d_in[4];
    const float* lng  = (const float*)d_in[5];
    const float* lnb  = (const float*)d_in[6];
    const float* qaw  = (const float*)d_in[7];
    const float* qab  = (const float*)d_in[8];
    float* out = (float*)d_out;

    cudaFuncSetAttribute(wspec_kernel,    cudaFuncAttributeMaxDynamicSharedMemorySize, WSPEC_SMEM);
    cudaFuncSetAttribute(conv_all_kernel, cudaFuncAttributeMaxDynamicSharedMemorySize, CONV_SMEM);

    embed_kernel<<<dim3(128, DMODEL / 32), dim3(32, 32)>>>(ids, emb, pos);
    wspec_kernel<<<NLAYERS * (DMODEL / 2), TTHR, WSPEC_SMEM>>>(fw);
    conv_all_kernel<<<DMODEL, TTHR, CONV_SMEM>>>(fb);
    final_kernel<<<dim3(128, 2), dim3(32, 32)>>>(lng, lnb, qaw, qab, out);
}